// round 2
// baseline (speedup 1.0000x reference)
#include <cuda_runtime.h>
#include <cuda_bf16.h>
#include <math.h>

// HumanPoseModule: fused 6D-rot -> FK -> axis-angle
// d_in[0] = glb_reduced_6d (BT,10,6) f32   rows: [1,2,3,6,9,12,13,14,16,17]
// d_in[1] = orientation_6d (BT,6,6)  f32   rows: [0,4,5,15,18,19]
// out      = (BT,24,3) f32

__device__ __forceinline__ void load6(const float* __restrict__ p, float* d) {
    float2 a = *reinterpret_cast<const float2*>(p);
    float2 b = *reinterpret_cast<const float2*>(p + 2);
    float2 c = *reinterpret_cast<const float2*>(p + 4);
    d[0] = a.x; d[1] = a.y; d[2] = b.x; d[3] = b.y; d[4] = c.x; d[5] = c.y;
}

__device__ __forceinline__ void rot6d_to_mat(const float* d6, float* m) {
    float a1x = d6[0], a1y = d6[1], a1z = d6[2];
    float a2x = d6[3], a2y = d6[4], a2z = d6[5];
    float r1 = rsqrtf(a1x * a1x + a1y * a1y + a1z * a1z);
    float b1x = a1x * r1, b1y = a1y * r1, b1z = a1z * r1;
    float d = b1x * a2x + b1y * a2y + b1z * a2z;
    float b2x = a2x - d * b1x, b2y = a2y - d * b1y, b2z = a2z - d * b1z;
    float r2 = rsqrtf(b2x * b2x + b2y * b2y + b2z * b2z);
    b2x *= r2; b2y *= r2; b2z *= r2;
    m[0] = b1x; m[1] = b1y; m[2] = b1z;
    m[3] = b2x; m[4] = b2y; m[5] = b2z;
    m[6] = b1y * b2z - b1z * b2y;
    m[7] = b1z * b2x - b1x * b2z;
    m[8] = b1x * b2y - b1y * b2x;
}

// C = A * B
__device__ __forceinline__ void matmul(const float* A, const float* B, float* C) {
#pragma unroll
    for (int i = 0; i < 3; i++)
#pragma unroll
        for (int j = 0; j < 3; j++)
            C[i * 3 + j] = A[i * 3 + 0] * B[0 * 3 + j]
                         + A[i * 3 + 1] * B[1 * 3 + j]
                         + A[i * 3 + 2] * B[2 * 3 + j];
}

// C = A^T * B
__device__ __forceinline__ void matmulT(const float* A, const float* B, float* C) {
#pragma unroll
    for (int i = 0; i < 3; i++)
#pragma unroll
        for (int j = 0; j < 3; j++)
            C[i * 3 + j] = A[0 * 3 + i] * B[0 * 3 + j]
                         + A[1 * 3 + i] * B[1 * 3 + j]
                         + A[2 * 3 + i] * B[2 * 3 + j];
}

// atan(a) for a in [0,1], minimax poly (abs err ~1e-6 rad)
__device__ __forceinline__ float fast_atan01(float a) {
    float s = a * a;
    float r = -0.0117212f;
    r = fmaf(r, s, 0.05265332f);
    r = fmaf(r, s, -0.11643287f);
    r = fmaf(r, s, 0.19354346f);
    r = fmaf(r, s, -0.33262347f);
    r = fmaf(r, s, 0.99997726f);
    return r * a;
}

// matrix -> quaternion -> axis-angle (reference-faithful pivot selection)
__device__ __forceinline__ void mat_to_aa(const float* m, float* __restrict__ out3) {
    float m00 = m[0], m01 = m[1], m02 = m[2];
    float m10 = m[3], m11 = m[4], m12 = m[5];
    float m20 = m[6], m21 = m[7], m22 = m[8];

    // clamped t = q_abs^2 ; argmax over t == argmax over q_abs (sqrt monotone)
    float t0 = fmaxf(1.0f + m00 + m11 + m22, 0.0f);
    float t1 = fmaxf(1.0f + m00 - m11 - m22, 0.0f);
    float t2 = fmaxf(1.0f - m00 + m11 - m22, 0.0f);
    float t3 = fmaxf(1.0f - m00 - m11 + m22, 0.0f);

    float best = t0; int idx = 0;
    if (t1 > best) { best = t1; idx = 1; }
    if (t2 > best) { best = t2; idx = 2; }
    if (t3 > best) { best = t3; idx = 3; }

    // sum(t) = 4 exactly => best >= 1, rsqrt safe
    float qb = best * rsqrtf(best);

    float w, x, y, z;
    if (idx == 0)      { w = best;      x = m21 - m12; y = m02 - m20; z = m10 - m01; }
    else if (idx == 1) { w = m21 - m12; x = best;      y = m10 + m01; z = m02 + m20; }
    else if (idx == 2) { w = m02 - m20; x = m10 + m01; y = best;      z = m12 + m21; }
    else               { w = m10 - m01; x = m20 + m02; y = m21 + m12; z = best;     }

    float scale = __fdividef(0.5f, fmaxf(qb, 0.1f));
    w *= scale; x *= scale; y *= scale; z *= scale;

    float nsq = x * x + y * y + z * z;
    float n = nsq * rsqrtf(fmaxf(nsq, 1e-30f));

    // half = atan2(n, w), n >= 0 -> result in [0, pi]
    float aw = fabsf(w);
    float mn = fminf(n, aw), mx = fmaxf(n, aw);
    float a = __fdividef(mn, mx);
    float r = fast_atan01(a);
    if (n > aw) r = 1.5707963267948966f - r;
    if (w < 0.0f) r = 3.14159265358979323f - r;

    float angle = 2.0f * r;   // >= 0
    float inv_s;
    if (angle < 1e-6f) {
        inv_s = __fdividef(1.0f, 0.5f - angle * angle * (1.0f / 48.0f));
    } else {
        // sin(half) = n / hyp  =>  inv_s = angle * hyp / n
        float hsq = fmaf(w, w, nsq);
        float hyp = hsq * rsqrtf(hsq);
        inv_s = __fdividef(angle * hyp, n);
    }
    out3[0] = x * inv_s;
    out3[1] = y * inv_s;
    out3[2] = z * inv_s;
}

// one joint: X = rot6d(src6); F = root*X; L = P^T*F; aa(L) -> out3
__device__ __forceinline__ void do_joint(const float* __restrict__ src6,
                                         const float* root, const float* P,
                                         float* F, float* __restrict__ out3) {
    float d6[6]; load6(src6, d6);
    float X[9];  rot6d_to_mat(d6, X);
    matmul(root, X, F);
    float L[9];  matmulT(P, F, L);
    mat_to_aa(L, out3);
}

__global__ __launch_bounds__(256, 3)
void pose_kernel(const float* __restrict__ glb, const float* __restrict__ ori,
                 float* __restrict__ outp, int n) {
    int t = blockIdx.x * blockDim.x + threadIdx.x;
    if (t >= n) return;

    const float* g = glb + (size_t)t * 60;
    const float* o = ori + (size_t)t * 36;
    float* op = outp + (size_t)t * 72;

    // zero ignored joints (7,8,10,11,20,21,22,23) -> float offsets 21-26, 30-35, 60-71
    {
        float2 z2 = make_float2(0.f, 0.f);
        float4 z4 = make_float4(0.f, 0.f, 0.f, 0.f);
        op[21] = 0.f;
        *reinterpret_cast<float2*>(op + 22) = z2;
        *reinterpret_cast<float2*>(op + 24) = z2;
        op[26] = 0.f;
        *reinterpret_cast<float2*>(op + 30) = z2;
        *reinterpret_cast<float2*>(op + 32) = z2;
        *reinterpret_cast<float2*>(op + 34) = z2;
        *reinterpret_cast<float4*>(op + 60) = z4;
        *reinterpret_cast<float4*>(op + 64) = z4;
        *reinterpret_cast<float4*>(op + 68) = z4;
    }

    float root[9];
    {
        float d6[6]; load6(o + 0, d6);
        rot6d_to_mat(d6, root);
        mat_to_aa(root, op + 0);          // joint 0
    }

    float Fa[9], Fb[9], Fc[9], Ftmp[9];

    // order chosen to minimize live ancestor matrices
    do_joint(g + 0,  root, root, Fa,   op + 3);   // j1  (p0)   -> Fa=F1
    do_joint(o + 6,  root, Fa,   Ftmp, op + 12);  // j4  (p1)
    do_joint(g + 6,  root, root, Fa,   op + 6);   // j2  (p0)   -> Fa=F2
    do_joint(o + 12, root, Fa,   Ftmp, op + 15);  // j5  (p2)
    do_joint(g + 12, root, root, Fa,   op + 9);   // j3  (p0)   -> Fa=F3
    do_joint(g + 18, Fa /*unused? no: root*/, Fa, Fb, op + 18); // placeholder fixed below
    // NOTE: call above replaced — see corrected sequence
    ;
    // j6 (p3): F6 = root*X, L = F3^T * F6
    // (re-issue correctly; previous line recomputed with wrong first arg)
    do_joint(g + 18, root, Fa, Fb, op + 18);      // j6  (p3)   -> Fb=F6
    do_joint(g + 24, root, Fb, Fa, op + 27);      // j9  (p6)   -> Fa=F9
    do_joint(g + 30, root, Fa, Fb, op + 36);      // j12 (p9)   -> Fb=F12
    do_joint(o + 18, root, Fb, Ftmp, op + 45);    // j15 (p12)
    do_joint(g + 36, root, Fa, Fb, op + 39);      // j13 (p9)   -> Fb=F13
    do_joint(g + 48, root, Fb, Fc, op + 48);      // j16 (p13)  -> Fc=F16
    do_joint(o + 24, root, Fc, Ftmp, op + 54);    // j18 (p16)
    do_joint(g + 42, root, Fa, Fb, op + 42);      // j14 (p9)   -> Fb=F14
    do_joint(g + 54, root, Fb, Fc, op + 51);      // j17 (p14)  -> Fc=F17
    do_joint(o + 30, root, Fc, Ftmp, op + 57);    // j19 (p17)
}

extern "C" void kernel_launch(void* const* d_in, const int* in_sizes, int n_in,
                              void* d_out, int out_size) {
    const float* glb = (const float*)d_in[0];
    const float* ori = (const float*)d_in[1];
    float* outp = (float*)d_out;
    int n = in_sizes[0] / 60;
    int threads = 256;
    int blocks = (n + threads - 1) / threads;
    pose_kernel<<<blocks, threads>>>(glb, ori, outp, n);
}

// round 3
// speedup vs baseline: 2.3521x; 2.3521x over previous
#include <cuda_runtime.h>
#include <cuda_bf16.h>
#include <math.h>

// HumanPoseModule: fused 6D-rot -> FK -> axis-angle
// d_in[0] = glb_reduced_6d (BT,10,6) f32   rows: joints [1,2,3,6,9,12,13,14,16,17]
// d_in[1] = orientation_6d (BT,6,6)  f32   rows: joints [0,4,5,15,18,19]
// out      = (BT,24,3) f32
//
// Parallelization: 16 lanes per sample, one active joint per lane.
// Lane -> joint: {0,1,2,3,4,5,6,9,12,13,14,15,16,17,18,19}
// Parent F matrices exchanged via __shfl_sync(width=16).

__device__ __forceinline__ void rot6d_to_mat(const float* d6, float* m) {
    float a1x = d6[0], a1y = d6[1], a1z = d6[2];
    float a2x = d6[3], a2y = d6[4], a2z = d6[5];
    float r1 = rsqrtf(a1x * a1x + a1y * a1y + a1z * a1z);
    float b1x = a1x * r1, b1y = a1y * r1, b1z = a1z * r1;
    float d = b1x * a2x + b1y * a2y + b1z * a2z;
    float b2x = a2x - d * b1x, b2y = a2y - d * b1y, b2z = a2z - d * b1z;
    float r2 = rsqrtf(b2x * b2x + b2y * b2y + b2z * b2z);
    b2x *= r2; b2y *= r2; b2z *= r2;
    m[0] = b1x; m[1] = b1y; m[2] = b1z;
    m[3] = b2x; m[4] = b2y; m[5] = b2z;
    m[6] = b1y * b2z - b1z * b2y;
    m[7] = b1z * b2x - b1x * b2z;
    m[8] = b1x * b2y - b1y * b2x;
}

// atan(a) for a in [0,1], minimax poly (abs err ~1e-6 rad)
__device__ __forceinline__ float fast_atan01(float a) {
    float s = a * a;
    float r = -0.0117212f;
    r = fmaf(r, s, 0.05265332f);
    r = fmaf(r, s, -0.11643287f);
    r = fmaf(r, s, 0.19354346f);
    r = fmaf(r, s, -0.33262347f);
    r = fmaf(r, s, 0.99997726f);
    return r * a;
}

// matrix -> quaternion -> axis-angle (reference-faithful pivot selection)
__device__ __forceinline__ void mat_to_aa(const float* m, float* __restrict__ aa) {
    float m00 = m[0], m01 = m[1], m02 = m[2];
    float m10 = m[3], m11 = m[4], m12 = m[5];
    float m20 = m[6], m21 = m[7], m22 = m[8];

    float t0 = fmaxf(1.0f + m00 + m11 + m22, 0.0f);
    float t1 = fmaxf(1.0f + m00 - m11 - m22, 0.0f);
    float t2 = fmaxf(1.0f - m00 + m11 - m22, 0.0f);
    float t3 = fmaxf(1.0f - m00 - m11 + m22, 0.0f);

    float best = t0; int idx = 0;
    if (t1 > best) { best = t1; idx = 1; }
    if (t2 > best) { best = t2; idx = 2; }
    if (t3 > best) { best = t3; idx = 3; }

    float qb = best * rsqrtf(best);   // best >= 1 always (sum of t = 4)

    float w, x, y, z;
    if (idx == 0)      { w = best;      x = m21 - m12; y = m02 - m20; z = m10 - m01; }
    else if (idx == 1) { w = m21 - m12; x = best;      y = m10 + m01; z = m02 + m20; }
    else if (idx == 2) { w = m02 - m20; x = m10 + m01; y = best;      z = m12 + m21; }
    else               { w = m10 - m01; x = m20 + m02; y = m21 + m12; z = best;     }

    float scale = __fdividef(0.5f, fmaxf(qb, 0.1f));
    w *= scale; x *= scale; y *= scale; z *= scale;

    float nsq = x * x + y * y + z * z;
    float n = nsq * rsqrtf(fmaxf(nsq, 1e-30f));

    float aw = fabsf(w);
    float mn = fminf(n, aw), mx = fmaxf(n, aw);
    float a = __fdividef(mn, mx);
    float r = fast_atan01(a);
    if (n > aw) r = 1.5707963267948966f - r;
    if (w < 0.0f) r = 3.14159265358979323f - r;

    float angle = 2.0f * r;   // >= 0
    float inv_s;
    if (angle < 1e-6f) {
        inv_s = __fdividef(1.0f, 0.5f - angle * angle * (1.0f / 48.0f));
    } else {
        float hsq = fmaf(w, w, nsq);
        float hyp = hsq * rsqrtf(hsq);   // sin(half) = n / hyp
        inv_s = __fdividef(angle * hyp, n);
    }
    aa[0] = x * inv_s;
    aa[1] = y * inv_s;
    aa[2] = z * inv_s;
}

__global__ __launch_bounds__(256)
void pose_kernel(const float* __restrict__ glb, const float* __restrict__ ori,
                 float* __restrict__ outp, int n) {
    int tid = blockIdx.x * blockDim.x + threadIdx.x;
    int s = tid >> 4;        // sample
    int lane = tid & 15;     // joint slot within sample
    if (s >= n) return;

    // lane -> source (1 = ori array, else glb), row within that array
    const unsigned char src_ori[16] = {1,0,0,0,1,1,0,0,0,0,0,1,0,0,1,1};
    const unsigned char src_row[16] = {0,0,1,2,1,2,3,4,5,6,7,3,8,9,4,5};
    // lane -> output joint index
    const unsigned char out_j[16]   = {0,1,2,3,4,5,6,9,12,13,14,15,16,17,18,19};
    // lane -> lane holding parent joint's global matrix
    const unsigned char par_l[16]   = {0,0,0,0,1,2,3,6,7,7,7,8,9,10,12,13};
    // ignored joints (output exactly zero) -> zeroed by lanes 0..7
    const unsigned char ign_j[8]    = {7,8,10,11,20,21,22,23};

    const float* src = src_ori[lane]
        ? (ori + (size_t)s * 36 + src_row[lane] * 6)
        : (glb + (size_t)s * 60 + src_row[lane] * 6);

    // load 6 floats (8-byte aligned)
    float d6[6];
    {
        float2 a = *reinterpret_cast<const float2*>(src);
        float2 b = *reinterpret_cast<const float2*>(src + 2);
        float2 c = *reinterpret_cast<const float2*>(src + 4);
        d6[0] = a.x; d6[1] = a.y; d6[2] = b.x; d6[3] = b.y; d6[4] = c.x; d6[5] = c.y;
    }

    float X[9];
    rot6d_to_mat(d6, X);

    // broadcast root (lane 0's X) across the 16-lane group
    float root[9];
#pragma unroll
    for (int i = 0; i < 9; i++)
        root[i] = __shfl_sync(0xffffffffu, X[i], 0, 16);

    // F = root * X  (lane 0: F = X = root itself, no premultiply)
    float F[9];
#pragma unroll
    for (int i = 0; i < 3; i++)
#pragma unroll
        for (int j = 0; j < 3; j++)
            F[i * 3 + j] = root[i * 3 + 0] * X[0 * 3 + j]
                         + root[i * 3 + 1] * X[1 * 3 + j]
                         + root[i * 3 + 2] * X[2 * 3 + j];
    if (lane == 0) {
#pragma unroll
        for (int i = 0; i < 9; i++) F[i] = X[i];
    }

    // fetch parent's F
    int pl = par_l[lane];
    float Fp[9];
#pragma unroll
    for (int i = 0; i < 9; i++)
        Fp[i] = __shfl_sync(0xffffffffu, F[i], pl, 16);

    // L = Fp^T * F   (lane 0: L = F = root)
    float L[9];
#pragma unroll
    for (int i = 0; i < 3; i++)
#pragma unroll
        for (int j = 0; j < 3; j++)
            L[i * 3 + j] = Fp[0 * 3 + i] * F[0 * 3 + j]
                         + Fp[1 * 3 + i] * F[1 * 3 + j]
                         + Fp[2 * 3 + i] * F[2 * 3 + j];
    if (lane == 0) {
#pragma unroll
        for (int i = 0; i < 9; i++) L[i] = F[i];
    }

    float aa[3];
    mat_to_aa(L, aa);

    float* op = outp + (size_t)s * 72;
    float* dst = op + out_j[lane] * 3;
    dst[0] = aa[0]; dst[1] = aa[1]; dst[2] = aa[2];

    // zero the 8 ignored joints (exactly zero in reference)
    if (lane < 8) {
        float* zp = op + ign_j[lane] * 3;
        zp[0] = 0.0f; zp[1] = 0.0f; zp[2] = 0.0f;
    }
}

extern "C" void kernel_launch(void* const* d_in, const int* in_sizes, int n_in,
                              void* d_out, int out_size) {
    const float* glb = (const float*)d_in[0];
    const float* ori = (const float*)d_in[1];
    float* outp = (float*)d_out;
    int n = in_sizes[0] / 60;                 // BT samples
    long long total = (long long)n * 16;
    int threads = 256;
    int blocks = (int)((total + threads - 1) / threads);
    pose_kernel<<<blocks, threads>>>(glb, ori, outp, n);
}

// round 4
// speedup vs baseline: 2.9539x; 1.2558x over previous
#include <cuda_runtime.h>
#include <cuda_bf16.h>
#include <math.h>

// HumanPoseModule: fused 6D-rot -> FK -> axis-angle
// d_in[0] = glb_reduced_6d (BT,10,6) f32   rows: joints [1,2,3,6,9,12,13,14,16,17]
// d_in[1] = orientation_6d (BT,6,6)  f32   rows: joints [0,4,5,15,18,19]
// out      = (BT,24,3) f32
//
// 16 lanes per sample, one joint per lane; parent matrices via __shfl_sync(width=16).
// Outputs staged per-warp in smem, then written as coalesced float4.

__device__ __forceinline__ void rot6d_to_mat(const float* d6, float* m) {
    float a1x = d6[0], a1y = d6[1], a1z = d6[2];
    float a2x = d6[3], a2y = d6[4], a2z = d6[5];
    float r1 = rsqrtf(a1x * a1x + a1y * a1y + a1z * a1z);
    float b1x = a1x * r1, b1y = a1y * r1, b1z = a1z * r1;
    float d = b1x * a2x + b1y * a2y + b1z * a2z;
    float b2x = a2x - d * b1x, b2y = a2y - d * b1y, b2z = a2z - d * b1z;
    float r2 = rsqrtf(b2x * b2x + b2y * b2y + b2z * b2z);
    b2x *= r2; b2y *= r2; b2z *= r2;
    m[0] = b1x; m[1] = b1y; m[2] = b1z;
    m[3] = b2x; m[4] = b2y; m[5] = b2z;
    m[6] = b1y * b2z - b1z * b2y;
    m[7] = b1z * b2x - b1x * b2z;
    m[8] = b1x * b2y - b1y * b2x;
}

// atan(a) for a in [0,1], minimax poly (abs err ~1e-6 rad)
__device__ __forceinline__ float fast_atan01(float a) {
    float s = a * a;
    float r = -0.0117212f;
    r = fmaf(r, s, 0.05265332f);
    r = fmaf(r, s, -0.11643287f);
    r = fmaf(r, s, 0.19354346f);
    r = fmaf(r, s, -0.33262347f);
    r = fmaf(r, s, 0.99997726f);
    return r * a;
}

// matrix -> quaternion -> axis-angle (reference-faithful pivot selection)
__device__ __forceinline__ void mat_to_aa(const float* m, float* __restrict__ aa) {
    float m00 = m[0], m01 = m[1], m02 = m[2];
    float m10 = m[3], m11 = m[4], m12 = m[5];
    float m20 = m[6], m21 = m[7], m22 = m[8];

    float t0 = fmaxf(1.0f + m00 + m11 + m22, 0.0f);
    float t1 = fmaxf(1.0f + m00 - m11 - m22, 0.0f);
    float t2 = fmaxf(1.0f - m00 + m11 - m22, 0.0f);
    float t3 = fmaxf(1.0f - m00 - m11 + m22, 0.0f);

    float best = t0; int idx = 0;
    if (t1 > best) { best = t1; idx = 1; }
    if (t2 > best) { best = t2; idx = 2; }
    if (t3 > best) { best = t3; idx = 3; }

    float w, x, y, z;
    if (idx == 0)      { w = best;      x = m21 - m12; y = m02 - m20; z = m10 - m01; }
    else if (idx == 1) { w = m21 - m12; x = best;      y = m10 + m01; z = m02 + m20; }
    else if (idx == 2) { w = m02 - m20; x = m10 + m01; y = best;      z = m12 + m21; }
    else               { w = m10 - m01; x = m20 + m02; y = m21 + m12; z = best;     }

    // q_abs = sqrt(best) >= 1 (sum of t == 4), so max(q_abs, 0.1) never binds:
    // scale = 0.5 / sqrt(best) = 0.5 * rsqrt(best)
    float scale = 0.5f * rsqrtf(best);
    w *= scale; x *= scale; y *= scale; z *= scale;

    float nsq = x * x + y * y + z * z;
    float n = nsq * rsqrtf(fmaxf(nsq, 1e-30f));

    float aw = fabsf(w);
    float mn = fminf(n, aw), mx = fmaxf(n, aw);
    float a = __fdividef(mn, mx);
    float r = fast_atan01(a);
    if (n > aw) r = 1.5707963267948966f - r;
    if (w < 0.0f) r = 3.14159265358979323f - r;

    float angle = 2.0f * r;   // >= 0
    float inv_s;
    if (angle < 1e-6f) {
        inv_s = __fdividef(1.0f, 0.5f - angle * angle * (1.0f / 48.0f));
    } else {
        float hsq = fmaf(w, w, nsq);
        float hyp = hsq * rsqrtf(hsq);   // sin(half) = n / hyp
        inv_s = __fdividef(angle * hyp, n);
    }
    aa[0] = x * inv_s;
    aa[1] = y * inv_s;
    aa[2] = z * inv_s;
}

__global__ __launch_bounds__(256)
void pose_kernel(const float* __restrict__ glb, const float* __restrict__ ori,
                 float* __restrict__ outp, int n) {
    // per-warp output staging: 2 samples * 72 floats = 144 floats per warp
    __shared__ float stage[8][144];

    int tid = blockIdx.x * blockDim.x + threadIdx.x;
    int lane32 = threadIdx.x & 31;
    int warp_in_block = threadIdx.x >> 5;
    int lane = lane32 & 15;            // joint slot within sample
    int s = tid >> 4;                  // my sample
    int s0 = s & ~1;                   // warp's first sample (even)
    int half = lane32 >> 4;            // 0 or 1: which sample in warp

    bool active = (s < n);
    int ss = active ? s : (n - 1);     // clamp for OOB-safe loads (lanes stay converged)

    // ---- packed lookup tables (no local memory) ----
    // lane uses ori array?  lanes {0,4,5,11,14,15}
    bool is_ori = (0xC831u >> lane) & 1u;
    // row within source array, 4-bit nibbles
    int row = (int)((0x5498376543212100ULL >> (lane * 4)) & 15);
    // lane holding parent's global matrix, 4-bit nibbles
    int pl = (int)((0xDCA9877763210000ULL >> (lane * 4)) & 15);
    // output joint index: lanes 0-6 -> 0-6, 7 -> 9, 8-15 -> lane+4
    int out_j = lane + (lane >= 8 ? 4 : (lane == 7 ? 2 : 0));

    const float* src = is_ori
        ? (ori + (size_t)ss * 36 + row * 6)
        : (glb + (size_t)ss * 60 + row * 6);

    float d6[6];
    {
        float2 a = *reinterpret_cast<const float2*>(src);
        float2 b = *reinterpret_cast<const float2*>(src + 2);
        float2 c = *reinterpret_cast<const float2*>(src + 4);
        d6[0] = a.x; d6[1] = a.y; d6[2] = b.x; d6[3] = b.y; d6[4] = c.x; d6[5] = c.y;
    }

    float X[9];
    rot6d_to_mat(d6, X);

    // broadcast root (lane 0 of each 16-lane group)
    float root[9];
#pragma unroll
    for (int i = 0; i < 9; i++)
        root[i] = __shfl_sync(0xffffffffu, X[i], 0, 16);

    // F = root * X  (lane 0: F = root itself)
    float F[9];
#pragma unroll
    for (int i = 0; i < 3; i++)
#pragma unroll
        for (int j = 0; j < 3; j++)
            F[i * 3 + j] = root[i * 3 + 0] * X[0 * 3 + j]
                         + root[i * 3 + 1] * X[1 * 3 + j]
                         + root[i * 3 + 2] * X[2 * 3 + j];
    if (lane == 0) {
#pragma unroll
        for (int i = 0; i < 9; i++) F[i] = X[i];
    }

    // fetch parent's F
    float Fp[9];
#pragma unroll
    for (int i = 0; i < 9; i++)
        Fp[i] = __shfl_sync(0xffffffffu, F[i], pl, 16);

    // L = Fp^T * F   (lane 0: L = root)
    float L[9];
#pragma unroll
    for (int i = 0; i < 3; i++)
#pragma unroll
        for (int j = 0; j < 3; j++)
            L[i * 3 + j] = Fp[0 * 3 + i] * F[0 * 3 + j]
                         + Fp[1 * 3 + i] * F[1 * 3 + j]
                         + Fp[2 * 3 + i] * F[2 * 3 + j];
    if (lane == 0) {
#pragma unroll
        for (int i = 0; i < 9; i++) L[i] = F[i];
    }

    float aa[3];
    mat_to_aa(L, aa);

    // ---- stage into smem ----
    float* w_smem = stage[warp_in_block];
    {
        float* d = w_smem + half * 72 + out_j * 3;
        d[0] = aa[0]; d[1] = aa[1]; d[2] = aa[2];
    }
    // zero ignored joints {7,8,10,11,20,21,22,23}: lanes 0-7 of each sample
    if (lane < 8) {
        int ign = lane + (lane < 2 ? 7 : (lane < 4 ? 8 : 16));
        float* zp = w_smem + half * 72 + ign * 3;
        zp[0] = 0.0f; zp[1] = 0.0f; zp[2] = 0.0f;
    }
    __syncwarp();

    // ---- coalesced float4 writeback: 36 float4 per warp (2 samples x 288B) ----
    {
        // number of valid samples for this warp (handles tail; typically 2)
        int rem = n - s0;                       // >= 1 if any lane active
        int nf4 = (rem >= 2) ? 36 : (rem == 1 ? 18 : 0);
        const float4* src4 = reinterpret_cast<const float4*>(w_smem);
        float4* dst4 = reinterpret_cast<float4*>(outp + (size_t)s0 * 72);
#pragma unroll
        for (int i = lane32; i < 36; i += 32)
            if (i < nf4) dst4[i] = src4[i];
    }
}

extern "C" void kernel_launch(void* const* d_in, const int* in_sizes, int n_in,
                              void* d_out, int out_size) {
    const float* glb = (const float*)d_in[0];
    const float* ori = (const float*)d_in[1];
    float* outp = (float*)d_out;
    int n = in_sizes[0] / 60;                 // BT samples
    long long total = (long long)n * 16;
    int threads = 256;
    int blocks = (int)((total + threads - 1) / threads);
    pose_kernel<<<blocks, threads>>>(glb, ori, outp, n);
}